// round 2
// baseline (speedup 1.0000x reference)
#include <cuda_runtime.h>

#define D_MODEL 256
#define ARITY 32
#define NDEPTH 15
#define VOCAB 1027
#define BATCH 8192
#define LN_EPS 1e-5f

// ---------------- scratch (device globals; no allocation allowed) -------------
__device__ __align__(16) float g_TP[VOCAB * D_MODEL];            // token proj + bias b folded
__device__ __align__(16) float g_DP[ARITY * NDEPTH * D_MODEL];   // depth proj + idx proj folded
__device__ __align__(16) float g_bias[BATCH * D_MODEL];          // per-row bias vector

// W layout (row-major [24832, 256]):
//   rows [0,256)                       : e_op (token) block
//   rows 256 + a*768 + [0,256)         : child-emb block a
//   rows 256 + a*768 + 256 + [0,256)   : depth block a
//   rows 256 + a*768 + 512 + [0,256)   : idx block a

// ---------------- K1: DP[a][d][:] = depth_emb[d] @ W_de_a + idx_emb[a] @ W_ie_a ---
__global__ void dp_kernel(const float* __restrict__ depth_emb,
                          const float* __restrict__ idx_emb,
                          const float* __restrict__ W) {
    __shared__ float de_s[NDEPTH * D_MODEL];
    __shared__ float ie_s[D_MODEL];
    const int a = blockIdx.x;
    const int j = threadIdx.x;  // output column 0..255

    for (int i = j; i < NDEPTH * D_MODEL; i += blockDim.x) de_s[i] = depth_emb[i];
    ie_s[j] = idx_emb[a * D_MODEL + j];
    __syncthreads();

    float acc[NDEPTH];
#pragma unroll
    for (int m = 0; m < NDEPTH; m++) acc[m] = 0.f;
    float acci = 0.f;

    const float* Wde = W + (size_t)(512 + a * 768) * D_MODEL + j;  // 256+a*768+256
    const float* Wie = W + (size_t)(768 + a * 768) * D_MODEL + j;  // 256+a*768+512
    for (int k = 0; k < D_MODEL; k++) {
        float wde = Wde[k * D_MODEL];
        float wie = Wie[k * D_MODEL];
        acci = fmaf(ie_s[k], wie, acci);
#pragma unroll
        for (int m = 0; m < NDEPTH; m++)
            acc[m] = fmaf(de_s[m * D_MODEL + k], wde, acc[m]);
    }
#pragma unroll
    for (int m = 0; m < NDEPTH; m++)
        g_DP[(a * NDEPTH + m) * D_MODEL + j] = acc[m] + acci;
}

// ---------------- K2: TP[v][:] = b + token_emb[v] @ W_tok ---------------------
__global__ void tp_kernel(const float* __restrict__ token_emb,
                          const float* __restrict__ W,
                          const float* __restrict__ bvec) {
    __shared__ float te_s[8 * D_MODEL];
    const int v0 = blockIdx.x * 8;
    const int j = threadIdx.x;

#pragma unroll
    for (int m = 0; m < 8; m++) {
        int v = v0 + m;
        te_s[m * D_MODEL + j] = (v < VOCAB) ? token_emb[v * D_MODEL + j] : 0.f;
    }
    __syncthreads();

    float acc[8];
    float bj = bvec[j];
#pragma unroll
    for (int m = 0; m < 8; m++) acc[m] = bj;

    const float* Wt = W + j;  // token block starts at row 0
    for (int k = 0; k < D_MODEL; k++) {
        float w = Wt[k * D_MODEL];
#pragma unroll
        for (int m = 0; m < 8; m++)
            acc[m] = fmaf(te_s[m * D_MODEL + k], w, acc[m]);
    }
#pragma unroll
    for (int m = 0; m < 8; m++) {
        int v = v0 + m;
        if (v < VOCAB) g_TP[v * D_MODEL + j] = acc[m];
    }
}

// ---------------- K3: bias[b][:] = TP[nid[b]] + sum_a DP[a][depth[a][b]] ------
__global__ void bias_kernel(const int* __restrict__ nid,
                            const int* __restrict__ child_depths) {
    __shared__ int s_d[ARITY][32];
    __shared__ int s_n[32];
    const int b0 = blockIdx.x * 32;
    const int t = threadIdx.x;

    for (int i = t; i < ARITY * 32; i += 256) {
        int a = i >> 5, r = i & 31;
        s_d[a][r] = child_depths[a * BATCH + b0 + r];
    }
    if (t < 32) s_n[t] = nid[b0 + t];
    __syncthreads();

    const int j = t;  // column
    for (int r = 0; r < 32; r++) {
        float acc = g_TP[s_n[r] * D_MODEL + j];
#pragma unroll
        for (int a = 0; a < ARITY; a++)
            acc += g_DP[(a * NDEPTH + s_d[a][r]) * D_MODEL + j];
        g_bias[(b0 + r) * D_MODEL + j] = acc;
    }
}

// ---------------- K4: main GEMM (M=8192, K=8192, N=256) + bias + ReLU + LN ----
// BM=64, BN=256, BK=32. 256 threads, 8x8 micro-tile.
// warp ty owns rows [ty*8, ty*8+8) entirely -> LayerNorm = warp shuffle reduce.
__global__ __launch_bounds__(256)
void gemm_kernel(const float* __restrict__ child_embs,
                 const float* __restrict__ W,
                 const float* __restrict__ ln_g,
                 const float* __restrict__ ln_b,
                 float* __restrict__ out) {
    __shared__ float As[64][33];      // padded: conflict-free scalar stores + broadcast reads
    __shared__ float Bs[32][D_MODEL];

    const int t  = threadIdx.x;
    const int ty = t >> 5;        // warp id 0..7   -> rows ty*8..ty*8+7
    const int tx = t & 31;        // lane           -> cols tx*8..tx*8+7
    const int b0 = blockIdx.x * 64;

    // A-tile load mapping: thread loads rows (t>>3) and (t>>3)+32, cols (t&7)*4 .. +3
    const int am = t >> 3;
    const int ak = (t & 7) << 2;
    // B-tile load mapping: thread loads k-rows (t>>6)+4p, cols (t&63)*4 .. +3
    const int bk = t >> 6;
    const int bc = (t & 63) << 2;

    float acc[8][8];
#pragma unroll
    for (int i = 0; i < 8; i++)
#pragma unroll
        for (int j = 0; j < 8; j++) acc[i][j] = 0.f;

    for (int kt = 0; kt < 256; kt++) {
        const int a   = kt >> 3;
        const int kin = (kt & 7) << 5;

        const float* Ab = child_embs + ((size_t)(a * BATCH + b0)) * D_MODEL + kin;
        const float* Bb = W + ((size_t)(256 + a * 768 + kin)) * D_MODEL;

        float4 av0 = *(const float4*)(Ab + am * D_MODEL + ak);
        float4 av1 = *(const float4*)(Ab + (am + 32) * D_MODEL + ak);
        float4 bv[8];
#pragma unroll
        for (int p = 0; p < 8; p++)
            bv[p] = *(const float4*)(Bb + (bk + p * 4) * D_MODEL + bc);

        __syncthreads();  // previous tile consumed

        As[am][ak + 0] = av0.x; As[am][ak + 1] = av0.y;
        As[am][ak + 2] = av0.z; As[am][ak + 3] = av0.w;
        As[am + 32][ak + 0] = av1.x; As[am + 32][ak + 1] = av1.y;
        As[am + 32][ak + 2] = av1.z; As[am + 32][ak + 3] = av1.w;
#pragma unroll
        for (int p = 0; p < 8; p++)
            *(float4*)&Bs[bk + p * 4][bc] = bv[p];

        __syncthreads();

        const float* Ap = &As[ty * 8][0];
#pragma unroll
        for (int k = 0; k < 32; k++) {
            float af[8];
#pragma unroll
            for (int i = 0; i < 8; i++) af[i] = Ap[i * 33 + k];  // warp broadcast
            float4 bq0 = *(const float4*)&Bs[k][tx * 8];
            float4 bq1 = *(const float4*)&Bs[k][tx * 8 + 4];
            float bf[8] = {bq0.x, bq0.y, bq0.z, bq0.w, bq1.x, bq1.y, bq1.z, bq1.w};
#pragma unroll
            for (int i = 0; i < 8; i++)
#pragma unroll
                for (int j = 0; j < 8; j++)
                    acc[i][j] = fmaf(af[i], bf[j], acc[i][j]);
        }
    }

    // ---------------- epilogue: bias + ReLU + LayerNorm (warp-local) ----------
    float gj[8], lbj[8];
#pragma unroll
    for (int j = 0; j < 4; j++) {
        float4 g4 = *(const float4*)(ln_g + tx * 8 + (j >> 2) * 4);  // two float4s below
        (void)g4;
    }
    {
        float4 g0 = *(const float4*)(ln_g + tx * 8);
        float4 g1 = *(const float4*)(ln_g + tx * 8 + 4);
        float4 l0 = *(const float4*)(ln_b + tx * 8);
        float4 l1 = *(const float4*)(ln_b + tx * 8 + 4);
        gj[0]=g0.x; gj[1]=g0.y; gj[2]=g0.z; gj[3]=g0.w;
        gj[4]=g1.x; gj[5]=g1.y; gj[6]=g1.z; gj[7]=g1.w;
        lbj[0]=l0.x; lbj[1]=l0.y; lbj[2]=l0.z; lbj[3]=l0.w;
        lbj[4]=l1.x; lbj[5]=l1.y; lbj[6]=l1.z; lbj[7]=l1.w;
    }

#pragma unroll
    for (int i = 0; i < 8; i++) {
        const int row = b0 + ty * 8 + i;
        float4 bb0 = *(const float4*)(g_bias + (size_t)row * D_MODEL + tx * 8);
        float4 bb1 = *(const float4*)(g_bias + (size_t)row * D_MODEL + tx * 8 + 4);
        float h[8];
        h[0] = acc[i][0] + bb0.x; h[1] = acc[i][1] + bb0.y;
        h[2] = acc[i][2] + bb0.z; h[3] = acc[i][3] + bb0.w;
        h[4] = acc[i][4] + bb1.x; h[5] = acc[i][5] + bb1.y;
        h[6] = acc[i][6] + bb1.z; h[7] = acc[i][7] + bb1.w;

        float s = 0.f, ss = 0.f;
#pragma unroll
        for (int j = 0; j < 8; j++) {
            h[j] = fmaxf(h[j], 0.f);
            s += h[j];
            ss = fmaf(h[j], h[j], ss);
        }
#pragma unroll
        for (int o = 16; o > 0; o >>= 1) {
            s  += __shfl_xor_sync(0xFFFFFFFFu, s, o);
            ss += __shfl_xor_sync(0xFFFFFFFFu, ss, o);
        }
        const float mu  = s * (1.f / 256.f);
        const float var = ss * (1.f / 256.f) - mu * mu;
        const float rs  = rsqrtf(var + LN_EPS);

        float4 o0, o1;
        o0.x = (h[0] - mu) * rs * gj[0] + lbj[0];
        o0.y = (h[1] - mu) * rs * gj[1] + lbj[1];
        o0.z = (h[2] - mu) * rs * gj[2] + lbj[2];
        o0.w = (h[3] - mu) * rs * gj[3] + lbj[3];
        o1.x = (h[4] - mu) * rs * gj[4] + lbj[4];
        o1.y = (h[5] - mu) * rs * gj[5] + lbj[5];
        o1.z = (h[6] - mu) * rs * gj[6] + lbj[6];
        o1.w = (h[7] - mu) * rs * gj[7] + lbj[7];
        *(float4*)(out + (size_t)row * D_MODEL + tx * 8)     = o0;
        *(float4*)(out + (size_t)row * D_MODEL + tx * 8 + 4) = o1;
    }
}

// ---------------- launch --------------------------------------------------------
extern "C" void kernel_launch(void* const* d_in, const int* in_sizes, int n_in,
                              void* d_out, int out_size) {
    const int*   nid          = (const int*)d_in[0];
    const float* child_embs   = (const float*)d_in[1];
    const int*   child_depths = (const int*)d_in[2];
    const float* token_emb    = (const float*)d_in[3];
    const float* depth_emb    = (const float*)d_in[4];
    const float* idx_emb      = (const float*)d_in[5];
    const float* W            = (const float*)d_in[6];
    const float* bvec         = (const float*)d_in[7];
    const float* ln_g         = (const float*)d_in[8];
    const float* ln_b         = (const float*)d_in[9];
    float* out = (float*)d_out;

    dp_kernel<<<ARITY, 256>>>(depth_emb, idx_emb, W);
    tp_kernel<<<(VOCAB + 7) / 8, 256>>>(token_emb, W, bvec);
    bias_kernel<<<BATCH / 32, 256>>>(nid, child_depths);
    gemm_kernel<<<BATCH / 64, 256>>>(child_embs, W, ln_g, ln_b, out);
}

// round 4
// speedup vs baseline: 1.9509x; 1.9509x over previous
#include <cuda_runtime.h>
#include <cuda_bf16.h>
#include <cstdint>

#define D_MODEL 256
#define ARITY 32
#define NDEPTH 15
#define VOCAB 1027
#define BATCH 8192
#define KTOT 8192
#define LN_EPS 1e-5f

// ------------------------- device scratch (no allocs allowed) -----------------
__device__ __align__(16) float g_TP[VOCAB * D_MODEL];
__device__ __align__(16) float g_DP[ARITY * NDEPTH * D_MODEL];
__device__ __align__(16) float g_h[(size_t)BATCH * D_MODEL];
__device__ __align__(16) __nv_bfloat16 g_WThi[(size_t)D_MODEL * KTOT];
__device__ __align__(16) __nv_bfloat16 g_WTlo[(size_t)D_MODEL * KTOT];

// W layout (row-major [24832, 256]):
//   rows [0,256)                     : token block
//   rows 256 + a*768 + [0,256)       : child-emb block a   (the real GEMM)
//   rows 256 + a*768 + 256 + [0,256) : depth block a
//   rows 256 + a*768 + 512 + [0,256) : idx block a

// ---------------- K1: DP[a][d][:] = depth_emb[d]@W_de_a + idx_emb[a]@W_ie_a ----
__global__ void dp_kernel(const float* __restrict__ depth_emb,
                          const float* __restrict__ idx_emb,
                          const float* __restrict__ W) {
    __shared__ float de_s[NDEPTH * D_MODEL];
    __shared__ float ie_s[D_MODEL];
    const int a = blockIdx.x;
    const int j = threadIdx.x;
    for (int i = j; i < NDEPTH * D_MODEL; i += blockDim.x) de_s[i] = depth_emb[i];
    ie_s[j] = idx_emb[a * D_MODEL + j];
    __syncthreads();

    float acc[NDEPTH];
#pragma unroll
    for (int m = 0; m < NDEPTH; m++) acc[m] = 0.f;
    float acci = 0.f;
    const float* Wde = W + (size_t)(512 + a * 768) * D_MODEL + j;
    const float* Wie = W + (size_t)(768 + a * 768) * D_MODEL + j;
    for (int k = 0; k < D_MODEL; k++) {
        float wde = Wde[k * D_MODEL];
        float wie = Wie[k * D_MODEL];
        acci = fmaf(ie_s[k], wie, acci);
#pragma unroll
        for (int m = 0; m < NDEPTH; m++)
            acc[m] = fmaf(de_s[m * D_MODEL + k], wde, acc[m]);
    }
#pragma unroll
    for (int m = 0; m < NDEPTH; m++)
        g_DP[(a * NDEPTH + m) * D_MODEL + j] = acc[m] + acci;
}

// ---------------- K2: TP[v][:] = b + token_emb[v] @ W_tok ---------------------
__global__ void tp_kernel(const float* __restrict__ token_emb,
                          const float* __restrict__ W,
                          const float* __restrict__ bvec) {
    __shared__ float te_s[8 * D_MODEL];
    const int v0 = blockIdx.x * 8;
    const int j = threadIdx.x;
#pragma unroll
    for (int m = 0; m < 8; m++) {
        int v = v0 + m;
        te_s[m * D_MODEL + j] = (v < VOCAB) ? token_emb[v * D_MODEL + j] : 0.f;
    }
    __syncthreads();
    float acc[8];
    float bj = bvec[j];
#pragma unroll
    for (int m = 0; m < 8; m++) acc[m] = bj;
    const float* Wt = W + j;
    for (int k = 0; k < D_MODEL; k++) {
        float w = Wt[k * D_MODEL];
#pragma unroll
        for (int m = 0; m < 8; m++)
            acc[m] = fmaf(te_s[m * D_MODEL + k], w, acc[m]);
    }
#pragma unroll
    for (int m = 0; m < 8; m++) {
        int v = v0 + m;
        if (v < VOCAB) g_TP[v * D_MODEL + j] = acc[m];
    }
}

// ---------------- K3: convert+transpose W child blocks -> WT_hi/WT_lo ---------
// block handles 32 k-rows x 256 n. read coalesced, transpose via smem.
__global__ __launch_bounds__(256)
void convW_kernel(const float* __restrict__ W) {
    __shared__ float ws[32][257];
    const int kc = blockIdx.x * 32;
    const int t = threadIdx.x;
#pragma unroll 4
    for (int r = 0; r < 32; r++) {
        int kg = kc + r;
        ws[r][t] = W[(size_t)(256 + (kg >> 8) * 768 + (kg & 255)) * D_MODEL + t];
    }
    __syncthreads();
    // thread t = output row n=t: 32 k values -> 16 u32 hi + 16 u32 lo
    uint32_t hi[16], lo[16];
#pragma unroll
    for (int p = 0; p < 16; p++) {
        float x0 = ws[2 * p][t], x1 = ws[2 * p + 1][t];
        uint32_t h;
        asm("cvt.rn.bf16x2.f32 %0, %1, %2;" : "=r"(h) : "f"(x1), "f"(x0));
        float f0 = __uint_as_float(h << 16);
        float f1 = __uint_as_float(h & 0xffff0000u);
        float r0 = x0 - f0, r1 = x1 - f1;
        uint32_t l;
        asm("cvt.rn.bf16x2.f32 %0, %1, %2;" : "=r"(l) : "f"(r1), "f"(r0));
        hi[p] = h; lo[p] = l;
    }
    uint4* ph = (uint4*)(g_WThi + (size_t)t * KTOT + kc);
    uint4* pl = (uint4*)(g_WTlo + (size_t)t * KTOT + kc);
#pragma unroll
    for (int q = 0; q < 4; q++) {
        ph[q] = make_uint4(hi[4 * q], hi[4 * q + 1], hi[4 * q + 2], hi[4 * q + 3]);
        pl[q] = make_uint4(lo[4 * q], lo[4 * q + 1], lo[4 * q + 2], lo[4 * q + 3]);
    }
}

// =============================== main GEMM ====================================
// h = A @ WT^T via mma.sync bf16x3. BM=128, BN=128, BK=64. grid (64,2), 256 thr.
#define SST 65536
#define AHI 0
#define ALO 16384
#define BHI 32768
#define BLO 49152
#define SMEM_BYTES 131072

__device__ __forceinline__ void cpa16(uint32_t s, const void* g) {
    asm volatile("cp.async.cg.shared.global [%0], [%1], 16;" :: "r"(s), "l"(g));
}
__device__ __forceinline__ void ldsm4(uint32_t* r, uint32_t a) {
    asm volatile("ldmatrix.sync.aligned.m8n8.x4.shared.b16 {%0,%1,%2,%3}, [%4];"
                 : "=r"(r[0]), "=r"(r[1]), "=r"(r[2]), "=r"(r[3]) : "r"(a));
}
__device__ __forceinline__ void mma_bf16(float* c, const uint32_t* a, const uint32_t* b) {
    asm volatile(
        "mma.sync.aligned.m16n8k16.row.col.f32.bf16.bf16.f32 "
        "{%0,%1,%2,%3}, {%4,%5,%6,%7}, {%8,%9}, {%0,%1,%2,%3};"
        : "+f"(c[0]), "+f"(c[1]), "+f"(c[2]), "+f"(c[3])
        : "r"(a[0]), "r"(a[1]), "r"(a[2]), "r"(a[3]), "r"(b[0]), "r"(b[1]));
}

__global__ __launch_bounds__(256, 1)
void gemm_kernel(const float* __restrict__ ce) {
    extern __shared__ char smem[];
    uint32_t sb;
    asm("{ .reg .u64 t; cvta.to.shared.u64 t, %1; cvt.u32.u64 %0, t; }"
        : "=r"(sb) : "l"(smem));
    const int t = threadIdx.x;
    const int lane = t & 31, w = t >> 5;
    const int wm = w & 3, wn = w >> 2;
    const int m0 = blockIdx.x * 128, n0 = blockIdx.y * 128;

    // ldmatrix lane addressing
    const int arow0 = wm * 32 + (lane & 7) + ((lane >> 3) & 1) * 8;
    const uint32_t axor = (uint32_t)((arow0 & 7) << 4);
    const uint32_t khA = (uint32_t)((lane >> 4) * 16);
    const int brow0 = wn * 64 + (lane & 7) + ((lane >> 4) & 1) * 8;
    const uint32_t bxor = (uint32_t)((lane & 7) << 4);
    const uint32_t khB = (uint32_t)(((lane >> 3) & 1) * 16);
    uint32_t arowb[2], browb[4];
#pragma unroll
    for (int i = 0; i < 2; i++) arowb[i] = (uint32_t)(arow0 + i * 16) * 128;
#pragma unroll
    for (int jp = 0; jp < 4; jp++) browb[jp] = (uint32_t)(brow0 + jp * 16) * 128;

    // A prefetch / STS mapping
    const int prow = t >> 1, phalf = t & 1;
    const uint32_t prx = (uint32_t)((prow & 7) << 4);
    // B cp.async mapping
    const int bro = t >> 3, bo = t & 7;

    float acc[2][8][4];
#pragma unroll
    for (int i = 0; i < 2; i++)
#pragma unroll
        for (int j = 0; j < 8; j++)
#pragma unroll
            for (int q = 0; q < 4; q++) acc[i][j][q] = 0.f;

    float4 av[8];

    auto loadB = [&](int s, int buf) {
        const size_t kg = (size_t)s * 64;
        const uint32_t dhi = sb + buf * SST + BHI;
        const uint32_t dlo = sb + buf * SST + BLO;
#pragma unroll
        for (int i = 0; i < 4; i++) {
            int row = bro + i * 32;
            uint32_t so = (uint32_t)row * 128 + (((uint32_t)bo * 16) ^ ((uint32_t)(row & 7) << 4));
            const size_t go = (size_t)(n0 + row) * KTOT + kg + bo * 8;
            cpa16(dhi + so, g_WThi + go);
            cpa16(dlo + so, g_WTlo + go);
        }
    };
    auto loadA = [&](int s) {
        const int a = s >> 2, kin = (s & 3) * 64;
        const float* p = ce + ((size_t)a * BATCH + m0 + prow) * D_MODEL + kin + phalf * 32;
#pragma unroll
        for (int j = 0; j < 8; j++) av[j] = *(const float4*)(p + j * 4);
    };
    auto stsA = [&](int buf) {
        const uint32_t dhi = sb + buf * SST + AHI;
        const uint32_t dlo = sb + buf * SST + ALO;
        const uint32_t rbase = (uint32_t)prow * 128;
#pragma unroll
        for (int j = 0; j < 8; j++) {
            float x0 = av[j].x, x1 = av[j].y, x2 = av[j].z, x3 = av[j].w;
            uint32_t h01, h23, l01, l23;
            asm("cvt.rn.bf16x2.f32 %0, %1, %2;" : "=r"(h01) : "f"(x1), "f"(x0));
            asm("cvt.rn.bf16x2.f32 %0, %1, %2;" : "=r"(h23) : "f"(x3), "f"(x2));
            float r0 = x0 - __uint_as_float(h01 << 16);
            float r1 = x1 - __uint_as_float(h01 & 0xffff0000u);
            float r2 = x2 - __uint_as_float(h23 << 16);
            float r3 = x3 - __uint_as_float(h23 & 0xffff0000u);
            asm("cvt.rn.bf16x2.f32 %0, %1, %2;" : "=r"(l01) : "f"(r1), "f"(r0));
            asm("cvt.rn.bf16x2.f32 %0, %1, %2;" : "=r"(l23) : "f"(r3), "f"(r2));
            uint32_t off = rbase + (((uint32_t)(phalf * 64 + j * 8)) ^ prx);
            asm volatile("st.shared.v2.b32 [%0], {%1,%2};" :: "r"(dhi + off), "r"(h01), "r"(h23));
            asm volatile("st.shared.v2.b32 [%0], {%1,%2};" :: "r"(dlo + off), "r"(l01), "r"(l23));
        }
    };
    auto compute = [&](int buf) {
        const uint32_t SA0 = sb + buf * SST + AHI;
        const uint32_t SA1 = sb + buf * SST + ALO;
        const uint32_t SB0 = sb + buf * SST + BHI;
        const uint32_t SB1 = sb + buf * SST + BLO;
#pragma unroll
        for (int kk = 0; kk < 4; kk++) {
            uint32_t ah[2][4], al[2][4], bh[4][4], bl[4][4];
            const uint32_t ka = ((uint32_t)(kk * 32) + khA) ^ axor;
            const uint32_t kb = ((uint32_t)(kk * 32) + khB) ^ bxor;
#pragma unroll
            for (int i = 0; i < 2; i++) {
                ldsm4(ah[i], SA0 + arowb[i] + ka);
                ldsm4(al[i], SA1 + arowb[i] + ka);
            }
#pragma unroll
            for (int jp = 0; jp < 4; jp++) {
                ldsm4(bh[jp], SB0 + browb[jp] + kb);
                ldsm4(bl[jp], SB1 + browb[jp] + kb);
            }
#pragma unroll
            for (int i = 0; i < 2; i++)
#pragma unroll
                for (int j = 0; j < 8; j++) {
                    const int jp = j >> 1;
                    const uint32_t* bph = &bh[jp][(j & 1) * 2];
                    const uint32_t* bpl = &bl[jp][(j & 1) * 2];
                    mma_bf16(acc[i][j], ah[i], bph);
                    mma_bf16(acc[i][j], al[i], bph);
                    mma_bf16(acc[i][j], ah[i], bpl);
                }
        }
    };

    // prologue
    loadB(0, 0);
    loadA(0);
    stsA(0);
    asm volatile("cp.async.commit_group;" ::: "memory");
    asm volatile("cp.async.wait_group 0;" ::: "memory");
    __syncthreads();

    for (int s = 0; s < 128; s++) {
        const int buf = s & 1, nxt = buf ^ 1;
        if (s + 1 < 128) { loadB(s + 1, nxt); loadA(s + 1); }
        compute(buf);
        if (s + 1 < 128) {
            stsA(nxt);
            asm volatile("cp.async.commit_group;" ::: "memory");
            asm volatile("cp.async.wait_group 0;" ::: "memory");
        }
        __syncthreads();
    }

    // write h
#pragma unroll
    for (int i = 0; i < 2; i++)
#pragma unroll
        for (int j = 0; j < 8; j++) {
            const int r = m0 + wm * 32 + i * 16 + (lane >> 2);
            const int cidx = n0 + wn * 64 + j * 8 + (lane & 3) * 2;
            *(float2*)(g_h + (size_t)r * D_MODEL + cidx) =
                make_float2(acc[i][j][0], acc[i][j][1]);
            *(float2*)(g_h + (size_t)(r + 8) * D_MODEL + cidx) =
                make_float2(acc[i][j][2], acc[i][j][3]);
        }
}

// ---------------- K5: fused bias-gather + ReLU + LayerNorm --------------------
__global__ __launch_bounds__(256)
void ln_kernel(const int* __restrict__ nid, const int* __restrict__ cdep,
               const float* __restrict__ ln_g, const float* __restrict__ ln_b,
               float* __restrict__ out) {
    const int r = blockIdx.x * 8 + (threadIdx.x >> 5);
    const int lane = threadIdx.x & 31;
    const int cb = lane * 8;

    float4 x0 = *(const float4*)(g_h + (size_t)r * D_MODEL + cb);
    float4 x1 = *(const float4*)(g_h + (size_t)r * D_MODEL + cb + 4);
    const int tkn = nid[r];
    {
        const float* p = g_TP + tkn * D_MODEL + cb;
        float4 b0 = *(const float4*)p, b1 = *(const float4*)(p + 4);
        x0.x += b0.x; x0.y += b0.y; x0.z += b0.z; x0.w += b0.w;
        x1.x += b1.x; x1.y += b1.y; x1.z += b1.z; x1.w += b1.w;
    }
#pragma unroll
    for (int a = 0; a < ARITY; a++) {
        const int d = cdep[a * BATCH + r];
        const float* p = g_DP + (a * NDEPTH + d) * D_MODEL + cb;
        float4 b0 = *(const float4*)p, b1 = *(const float4*)(p + 4);
        x0.x += b0.x; x0.y += b0.y; x0.z += b0.z; x0.w += b0.w;
        x1.x += b1.x; x1.y += b1.y; x1.z += b1.z; x1.w += b1.w;
    }
    float h[8] = {x0.x, x0.y, x0.z, x0.w, x1.x, x1.y, x1.z, x1.w};
    float s = 0.f, ss = 0.f;
#pragma unroll
    for (int j = 0; j < 8; j++) {
        h[j] = fmaxf(h[j], 0.f);
        s += h[j];
        ss = fmaf(h[j], h[j], ss);
    }
#pragma unroll
    for (int o = 16; o > 0; o >>= 1) {
        s += __shfl_xor_sync(0xFFFFFFFFu, s, o);
        ss += __shfl_xor_sync(0xFFFFFFFFu, ss, o);
    }
    const float mu = s * (1.f / 256.f);
    const float rs = rsqrtf(ss * (1.f / 256.f) - mu * mu + LN_EPS);

    float4 g0 = *(const float4*)(ln_g + cb), g1 = *(const float4*)(ln_g + cb + 4);
    float4 l0 = *(const float4*)(ln_b + cb), l1 = *(const float4*)(ln_b + cb + 4);
    float4 o0, o1;
    o0.x = (h[0] - mu) * rs * g0.x + l0.x;
    o0.y = (h[1] - mu) * rs * g0.y + l0.y;
    o0.z = (h[2] - mu) * rs * g0.z + l0.z;
    o0.w = (h[3] - mu) * rs * g0.w + l0.w;
    o1.x = (h[4] - mu) * rs * g1.x + l1.x;
    o1.y = (h[5] - mu) * rs * g1.y + l1.y;
    o1.z = (h[6] - mu) * rs * g1.z + l1.z;
    o1.w = (h[7] - mu) * rs * g1.w + l1.w;
    *(float4*)(out + (size_t)r * D_MODEL + cb) = o0;
    *(float4*)(out + (size_t)r * D_MODEL + cb + 4) = o1;
}

// --------------------------------- launch -------------------------------------
extern "C" void kernel_launch(void* const* d_in, const int* in_sizes, int n_in,
                              void* d_out, int out_size) {
    const int*   nid          = (const int*)d_in[0];
    const float* child_embs   = (const float*)d_in[1];
    const int*   child_depths = (const int*)d_in[2];
    const float* token_emb    = (const float*)d_in[3];
    const float* depth_emb    = (const float*)d_in[4];
    const float* idx_emb      = (const float*)d_in[5];
    const float* W            = (const float*)d_in[6];
    const float* bvec         = (const float*)d_in[7];
    const float* ln_g         = (const float*)d_in[8];
    const float* ln_b         = (const float*)d_in[9];
    float* out = (float*)d_out;

    cudaFuncSetAttribute(gemm_kernel, cudaFuncAttributeMaxDynamicSharedMemorySize, SMEM_BYTES);

    dp_kernel<<<ARITY, 256>>>(depth_emb, idx_emb, W);
    tp_kernel<<<(VOCAB + 7) / 8, 256>>>(token_emb, W, bvec);
    convW_kernel<<<KTOT / 32, 256>>>(W);
    gemm_kernel<<<dim3(BATCH / 128, 2), 256, SMEM_BYTES>>>(child_embs);
    ln_kernel<<<BATCH / 8, 256>>>(nid, child_depths, ln_g, ln_b, out);
}

// round 5
// speedup vs baseline: 2.7213x; 1.3949x over previous
#include <cuda_runtime.h>
#include <cuda_fp16.h>
#include <cstdint>

#define D_MODEL 256
#define ARITY 32
#define NDEPTH 15
#define VOCAB 1027
#define BATCH 8192
#define KTOT 8192
#define LN_EPS 1e-5f

// ------------------------- device scratch (no allocs allowed) -----------------
__device__ __align__(16) float g_TP[VOCAB * D_MODEL];
__device__ __align__(16) float g_DP[ARITY * NDEPTH * D_MODEL];
__device__ __align__(16) float g_h[(size_t)BATCH * D_MODEL];
__device__ __align__(16) __half g_WThi[(size_t)D_MODEL * KTOT];

// W layout (row-major [24832, 256]):
//   rows [0,256)                     : token block
//   rows 256 + a*768 + [0,256)       : child-emb block a   (the real GEMM)
//   rows 256 + a*768 + 256 + [0,256) : depth block a
//   rows 256 + a*768 + 512 + [0,256) : idx block a

// ================== fused prep kernel: dp (32) | tp (129) | convW (256) =======
#define DP_BLOCKS 32
#define TP_BLOCKS 129
#define CW_BLOCKS 256

__device__ void dp_body(int a, char* sbuf,
                        const float* __restrict__ depth_emb,
                        const float* __restrict__ idx_emb,
                        const float* __restrict__ W) {
    float* de_s = (float*)sbuf;              // 15*256
    float* ie_s = de_s + NDEPTH * D_MODEL;   // 256
    const int j = threadIdx.x;
    for (int i = j; i < NDEPTH * D_MODEL; i += blockDim.x) de_s[i] = depth_emb[i];
    ie_s[j] = idx_emb[a * D_MODEL + j];
    __syncthreads();

    float acc[NDEPTH];
#pragma unroll
    for (int m = 0; m < NDEPTH; m++) acc[m] = 0.f;
    float acci = 0.f;
    const float* Wde = W + (size_t)(512 + a * 768) * D_MODEL + j;
    const float* Wie = W + (size_t)(768 + a * 768) * D_MODEL + j;
#pragma unroll 4
    for (int k = 0; k < D_MODEL; k++) {
        float wde = Wde[k * D_MODEL];
        float wie = Wie[k * D_MODEL];
        acci = fmaf(ie_s[k], wie, acci);
#pragma unroll
        for (int m = 0; m < NDEPTH; m++)
            acc[m] = fmaf(de_s[m * D_MODEL + k], wde, acc[m]);
    }
#pragma unroll
    for (int m = 0; m < NDEPTH; m++)
        g_DP[(a * NDEPTH + m) * D_MODEL + j] = acc[m] + acci;
}

__device__ void tp_body(int blk, char* sbuf,
                        const float* __restrict__ token_emb,
                        const float* __restrict__ W,
                        const float* __restrict__ bvec) {
    float* te_s = (float*)sbuf;  // 8*256
    const int v0 = blk * 8;
    const int j = threadIdx.x;
#pragma unroll
    for (int m = 0; m < 8; m++) {
        int v = v0 + m;
        te_s[m * D_MODEL + j] = (v < VOCAB) ? token_emb[v * D_MODEL + j] : 0.f;
    }
    __syncthreads();
    float acc[8];
    float bj = bvec[j];
#pragma unroll
    for (int m = 0; m < 8; m++) acc[m] = bj;
    const float* Wt = W + j;
#pragma unroll 4
    for (int k = 0; k < D_MODEL; k++) {
        float w = Wt[k * D_MODEL];
#pragma unroll
        for (int m = 0; m < 8; m++)
            acc[m] = fmaf(te_s[m * D_MODEL + k], w, acc[m]);
    }
#pragma unroll
    for (int m = 0; m < 8; m++) {
        int v = v0 + m;
        if (v < VOCAB) g_TP[v * D_MODEL + j] = acc[m];
    }
}

__device__ void convW_body(int blk, char* sbuf, const float* __restrict__ W) {
    float (*ws)[257] = (float (*)[257])sbuf;  // 32 x 257 floats
    const int kc = blk * 32;
    const int t = threadIdx.x;
#pragma unroll 4
    for (int r = 0; r < 32; r++) {
        int kg = kc + r;
        ws[r][t] = W[(size_t)(256 + (kg >> 8) * 768 + (kg & 255)) * D_MODEL + t];
    }
    __syncthreads();
    uint32_t hi[16];
#pragma unroll
    for (int p = 0; p < 16; p++) {
        __half2 h = __floats2half2_rn(ws[2 * p][t], ws[2 * p + 1][t]);
        hi[p] = *(uint32_t*)&h;
    }
    uint4* ph = (uint4*)(g_WThi + (size_t)t * KTOT + kc);
#pragma unroll
    for (int q = 0; q < 4; q++)
        ph[q] = make_uint4(hi[4 * q], hi[4 * q + 1], hi[4 * q + 2], hi[4 * q + 3]);
}

__global__ __launch_bounds__(256)
void prep_kernel(const float* __restrict__ depth_emb,
                 const float* __restrict__ idx_emb,
                 const float* __restrict__ token_emb,
                 const float* __restrict__ W,
                 const float* __restrict__ bvec) {
    __shared__ __align__(16) char sbuf[32 * 257 * 4];
    const int b = blockIdx.x;
    if (b < DP_BLOCKS)                 dp_body(b, sbuf, depth_emb, idx_emb, W);
    else if (b < DP_BLOCKS + TP_BLOCKS) tp_body(b - DP_BLOCKS, sbuf, token_emb, W, bvec);
    else                               convW_body(b - DP_BLOCKS - TP_BLOCKS, sbuf, W);
}

// =============================== main GEMM ====================================
// h = A @ WT^T via mma.sync fp16x2: (Ahi+Alo)@Bhi. BM=128, BN=128, BK=64.
// grid (64,2), 256 threads. SMEM stage = Ahi 16K + Alo 16K + Bhi 16K = 48K, x2.
#define SST 49152
#define AHI 0
#define ALO 16384
#define BHI 32768
#define SMEM_BYTES 98304

__device__ __forceinline__ void cpa16(uint32_t s, const void* g) {
    asm volatile("cp.async.cg.shared.global [%0], [%1], 16;" :: "r"(s), "l"(g));
}
__device__ __forceinline__ void ldsm4(uint32_t* r, uint32_t a) {
    asm volatile("ldmatrix.sync.aligned.m8n8.x4.shared.b16 {%0,%1,%2,%3}, [%4];"
                 : "=r"(r[0]), "=r"(r[1]), "=r"(r[2]), "=r"(r[3]) : "r"(a));
}
__device__ __forceinline__ void mma_fp16(float* c, const uint32_t* a, const uint32_t* b) {
    asm volatile(
        "mma.sync.aligned.m16n8k16.row.col.f32.f16.f16.f32 "
        "{%0,%1,%2,%3}, {%4,%5,%6,%7}, {%8,%9}, {%0,%1,%2,%3};"
        : "+f"(c[0]), "+f"(c[1]), "+f"(c[2]), "+f"(c[3])
        : "r"(a[0]), "r"(a[1]), "r"(a[2]), "r"(a[3]), "r"(b[0]), "r"(b[1]));
}

__global__ __launch_bounds__(256, 1)
void gemm_kernel(const float* __restrict__ ce) {
    extern __shared__ char smem[];
    uint32_t sb;
    asm("{ .reg .u64 t; cvta.to.shared.u64 t, %1; cvt.u32.u64 %0, t; }"
        : "=r"(sb) : "l"(smem));
    const int t = threadIdx.x;
    const int lane = t & 31, w = t >> 5;
    const int wm = w & 3, wn = w >> 2;
    const int m0 = blockIdx.x * 128, n0 = blockIdx.y * 128;

    // ldmatrix lane addressing (identical byte layout to round-4, 2B elems)
    const int arow0 = wm * 32 + (lane & 7) + ((lane >> 3) & 1) * 8;
    const uint32_t axor = (uint32_t)((arow0 & 7) << 4);
    const uint32_t khA = (uint32_t)((lane >> 4) * 16);
    const int brow0 = wn * 64 + (lane & 7) + ((lane >> 4) & 1) * 8;
    const uint32_t bxor = (uint32_t)((lane & 7) << 4);
    const uint32_t khB = (uint32_t)(((lane >> 3) & 1) * 16);
    uint32_t arowb[2], browb[4];
#pragma unroll
    for (int i = 0; i < 2; i++) arowb[i] = (uint32_t)(arow0 + i * 16) * 128;
#pragma unroll
    for (int jp = 0; jp < 4; jp++) browb[jp] = (uint32_t)(brow0 + jp * 16) * 128;

    // A prefetch / STS mapping: thread -> row t/2, k-half t&1 (32 elems)
    const int prow = t >> 1, phalf = t & 1;
    const uint32_t prx = (uint32_t)((prow & 7) << 4);
    // B cp.async mapping
    const int bro = t >> 3, bo = t & 7;

    float acc[2][8][4];
#pragma unroll
    for (int i = 0; i < 2; i++)
#pragma unroll
        for (int j = 0; j < 8; j++)
#pragma unroll
            for (int q = 0; q < 4; q++) acc[i][j][q] = 0.f;

    float4 av[8];

    auto loadB = [&](int s, int buf) {
        const size_t kg = (size_t)s * 64;
        const uint32_t dhi = sb + buf * SST + BHI;
#pragma unroll
        for (int i = 0; i < 4; i++) {
            int row = bro + i * 32;
            uint32_t so = (uint32_t)row * 128 + (((uint32_t)bo * 16) ^ ((uint32_t)(row & 7) << 4));
            cpa16(dhi + so, g_WThi + (size_t)(n0 + row) * KTOT + kg + bo * 8);
        }
    };
    auto loadA = [&](int s) {
        const int a = s >> 2, kin = (s & 3) * 64;
        const float* p = ce + ((size_t)a * BATCH + m0 + prow) * D_MODEL + kin + phalf * 32;
#pragma unroll
        for (int j = 0; j < 8; j++) av[j] = *(const float4*)(p + j * 4);
    };
    auto stsA = [&](int buf) {
        const uint32_t dhi = sb + buf * SST + AHI;
        const uint32_t dlo = sb + buf * SST + ALO;
        const uint32_t rbase = (uint32_t)prow * 128;
#pragma unroll
        for (int j = 0; j < 8; j++) {
            __half2 h01 = __floats2half2_rn(av[j].x, av[j].y);
            __half2 h23 = __floats2half2_rn(av[j].z, av[j].w);
            float r0 = av[j].x - __low2float(h01);
            float r1 = av[j].y - __high2float(h01);
            float r2 = av[j].z - __low2float(h23);
            float r3 = av[j].w - __high2float(h23);
            __half2 l01 = __floats2half2_rn(r0, r1);
            __half2 l23 = __floats2half2_rn(r2, r3);
            uint32_t off = rbase + (((uint32_t)(phalf * 64 + j * 8)) ^ prx);
            asm volatile("st.shared.v2.b32 [%0], {%1,%2};"
                         :: "r"(dhi + off), "r"(*(uint32_t*)&h01), "r"(*(uint32_t*)&h23));
            asm volatile("st.shared.v2.b32 [%0], {%1,%2};"
                         :: "r"(dlo + off), "r"(*(uint32_t*)&l01), "r"(*(uint32_t*)&l23));
        }
    };
    auto compute = [&](int buf) {
        const uint32_t SA0 = sb + buf * SST + AHI;
        const uint32_t SA1 = sb + buf * SST + ALO;
        const uint32_t SB0 = sb + buf * SST + BHI;
#pragma unroll
        for (int kk = 0; kk < 4; kk++) {
            uint32_t ah[2][4], al[2][4], bh[4][4];
            const uint32_t ka = ((uint32_t)(kk * 32) + khA) ^ axor;
            const uint32_t kb = ((uint32_t)(kk * 32) + khB) ^ bxor;
#pragma unroll
            for (int i = 0; i < 2; i++) {
                ldsm4(ah[i], SA0 + arowb[i] + ka);
                ldsm4(al[i], SA1 + arowb[i] + ka);
            }
#pragma unroll
            for (int jp = 0; jp < 4; jp++)
                ldsm4(bh[jp], SB0 + browb[jp] + kb);
#pragma unroll
            for (int i = 0; i < 2; i++)
#pragma unroll
                for (int j = 0; j < 8; j++) {
                    const uint32_t* bph = &bh[j >> 1][(j & 1) * 2];
                    mma_fp16(acc[i][j], ah[i], bph);
                    mma_fp16(acc[i][j], al[i], bph);
                }
        }
    };

    // prologue
    loadB(0, 0);
    loadA(0);
    stsA(0);
    asm volatile("cp.async.commit_group;" ::: "memory");
    asm volatile("cp.async.wait_group 0;" ::: "memory");
    __syncthreads();

    for (int s = 0; s < 128; s++) {
        const int buf = s & 1, nxt = buf ^ 1;
        if (s + 1 < 128) { loadB(s + 1, nxt); loadA(s + 1); }
        compute(buf);
        if (s + 1 < 128) {
            stsA(nxt);
            asm volatile("cp.async.commit_group;" ::: "memory");
            asm volatile("cp.async.wait_group 0;" ::: "memory");
        }
        __syncthreads();
    }

    // write h
#pragma unroll
    for (int i = 0; i < 2; i++)
#pragma unroll
        for (int j = 0; j < 8; j++) {
            const int r = m0 + wm * 32 + i * 16 + (lane >> 2);
            const int cidx = n0 + wn * 64 + j * 8 + (lane & 3) * 2;
            *(float2*)(g_h + (size_t)r * D_MODEL + cidx) =
                make_float2(acc[i][j][0], acc[i][j][1]);
            *(float2*)(g_h + (size_t)(r + 8) * D_MODEL + cidx) =
                make_float2(acc[i][j][2], acc[i][j][3]);
        }
}

// ---------------- fused bias-gather + ReLU + LayerNorm ------------------------
__global__ __launch_bounds__(256)
void ln_kernel(const int* __restrict__ nid, const int* __restrict__ cdep,
               const float* __restrict__ ln_g, const float* __restrict__ ln_b,
               float* __restrict__ out) {
    const int r = blockIdx.x * 8 + (threadIdx.x >> 5);
    const int lane = threadIdx.x & 31;
    const int cb = lane * 8;

    float4 x0 = *(const float4*)(g_h + (size_t)r * D_MODEL + cb);
    float4 x1 = *(const float4*)(g_h + (size_t)r * D_MODEL + cb + 4);
    const int tkn = nid[r];
    {
        const float* p = g_TP + tkn * D_MODEL + cb;
        float4 b0 = *(const float4*)p, b1 = *(const float4*)(p + 4);
        x0.x += b0.x; x0.y += b0.y; x0.z += b0.z; x0.w += b0.w;
        x1.x += b1.x; x1.y += b1.y; x1.z += b1.z; x1.w += b1.w;
    }
#pragma unroll
    for (int a = 0; a < ARITY; a++) {
        const int d = cdep[a * BATCH + r];
        const float* p = g_DP + (a * NDEPTH + d) * D_MODEL + cb;
        float4 b0 = *(const float4*)p, b1 = *(const float4*)(p + 4);
        x0.x += b0.x; x0.y += b0.y; x0.z += b0.z; x0.w += b0.w;
        x1.x += b1.x; x1.y += b1.y; x1.z += b1.z; x1.w += b1.w;
    }
    float h[8] = {x0.x, x0.y, x0.z, x0.w, x1.x, x1.y, x1.z, x1.w};
    float s = 0.f, ss = 0.f;
#pragma unroll
    for (int j = 0; j < 8; j++) {
        h[j] = fmaxf(h[j], 0.f);
        s += h[j];
        ss = fmaf(h[j], h[j], ss);
    }
#pragma unroll
    for (int o = 16; o > 0; o >>= 1) {
        s += __shfl_xor_sync(0xFFFFFFFFu, s, o);
        ss += __shfl_xor_sync(0xFFFFFFFFu, ss, o);
    }
    const float mu = s * (1.f / 256.f);
    const float rs = rsqrtf(ss * (1.f / 256.f) - mu * mu + LN_EPS);

    float4 g0 = *(const float4*)(ln_g + cb), g1 = *(const float4*)(ln_g + cb + 4);
    float4 l0 = *(const float4*)(ln_b + cb), l1 = *(const float4*)(ln_b + cb + 4);
    float4 o0, o1;
    o0.x = (h[0] - mu) * rs * g0.x + l0.x;
    o0.y = (h[1] - mu) * rs * g0.y + l0.y;
    o0.z = (h[2] - mu) * rs * g0.z + l0.z;
    o0.w = (h[3] - mu) * rs * g0.w + l0.w;
    o1.x = (h[4] - mu) * rs * g1.x + l1.x;
    o1.y = (h[5] - mu) * rs * g1.y + l1.y;
    o1.z = (h[6] - mu) * rs * g1.z + l1.z;
    o1.w = (h[7] - mu) * rs * g1.w + l1.w;
    *(float4*)(out + (size_t)r * D_MODEL + cb) = o0;
    *(float4*)(out + (size_t)r * D_MODEL + cb + 4) = o1;
}

// --------------------------------- launch -------------------------------------
extern "C" void kernel_launch(void* const* d_in, const int* in_sizes, int n_in,
                              void* d_out, int out_size) {
    const int*   nid          = (const int*)d_in[0];
    const float* child_embs   = (const float*)d_in[1];
    const int*   child_depths = (const int*)d_in[2];
    const float* token_emb    = (const float*)d_in[3];
    const float* depth_emb    = (const float*)d_in[4];
    const float* idx_emb      = (const float*)d_in[5];
    const float* W            = (const float*)d_in[6];
    const float* bvec         = (const float*)d_in[7];
    const float* ln_g         = (const float*)d_in[8];
    const float* ln_b         = (const float*)d_in[9];
    float* out = (float*)d_out;

    cudaFuncSetAttribute(gemm_kernel, cudaFuncAttributeMaxDynamicSharedMemorySize, SMEM_BYTES);

    prep_kernel<<<DP_BLOCKS + TP_BLOCKS + CW_BLOCKS, 256>>>(depth_emb, idx_emb, token_emb, W, bvec);
    gemm_kernel<<<dim3(BATCH / 128, 2), 256, SMEM_BYTES>>>(child_embs);
    ln_kernel<<<BATCH / 8, 256>>>(nid, child_depths, ln_g, ln_b, out);
}

// round 6
// speedup vs baseline: 6.4987x; 2.3881x over previous
#include <cuda_runtime.h>
#include <cuda_fp16.h>
#include <cstdint>

#define D_MODEL 256
#define ARITY 32
#define NDEPTH 15
#define VOCAB 1027
#define BATCH 8192
#define KTOT 8192
#define LN_EPS 1e-5f

// ------------------------- device scratch (no allocs allowed) -----------------
__device__ __align__(16) float g_TP[VOCAB * D_MODEL];
__device__ __align__(16) float g_DP[ARITY * NDEPTH * D_MODEL];
__device__ __align__(16) float g_h[(size_t)BATCH * D_MODEL];
__device__ __align__(16) __half g_WThi[(size_t)D_MODEL * KTOT];

// W layout (row-major [24832, 256]):
//   rows [0,256)                     : token block
//   rows 256 + a*768 + [0,256)       : child-emb block a   (the real GEMM)
//   rows 256 + a*768 + 256 + [0,256) : depth block a
//   rows 256 + a*768 + 512 + [0,256) : idx block a

// ---------------- convW: convert+transpose W child blocks -> WThi [256 x 8192] -
__global__ __launch_bounds__(256)
void convW_kernel(const float* __restrict__ W) {
    __shared__ float ws[32][257];
    const int kc = blockIdx.x * 32;
    const int t = threadIdx.x;
#pragma unroll 8
    for (int r = 0; r < 32; r++) {
        int kg = kc + r;
        ws[r][t] = W[(size_t)(256 + (kg >> 8) * 768 + (kg & 255)) * D_MODEL + t];
    }
    __syncthreads();
    uint32_t hi[16];
#pragma unroll
    for (int p = 0; p < 16; p++) {
        __half2 h = __floats2half2_rn(ws[2 * p][t], ws[2 * p + 1][t]);
        hi[p] = *(uint32_t*)&h;
    }
    uint4* ph = (uint4*)(g_WThi + (size_t)t * KTOT + kc);
#pragma unroll
    for (int q = 0; q < 4; q++)
        ph[q] = make_uint4(hi[4 * q], hi[4 * q + 1], hi[4 * q + 2], hi[4 * q + 3]);
}

// ================================ mega kernel ==================================
// blocks [0,128): GEMM  h = A @ WT^T, pure fp16, BM=64, BN=256, BK=64
// blocks [128,160): dp bodies   blocks [160,289): tp bodies (run on idle SMs)
#define GEMM_BLOCKS 128
#define DP_BLOCKS 32
#define TP_BLOCKS 129
#define SST 40960
#define BOFF 8192
#define SMEM_BYTES 81920

__device__ __forceinline__ void cpa16(uint32_t s, const void* g) {
    asm volatile("cp.async.cg.shared.global [%0], [%1], 16;" :: "r"(s), "l"(g));
}
__device__ __forceinline__ void ldsm4(uint32_t* r, uint32_t a) {
    asm volatile("ldmatrix.sync.aligned.m8n8.x4.shared.b16 {%0,%1,%2,%3}, [%4];"
                 : "=r"(r[0]), "=r"(r[1]), "=r"(r[2]), "=r"(r[3]) : "r"(a));
}
__device__ __forceinline__ void mma_fp16(float* c, const uint32_t* a, const uint32_t* b) {
    asm volatile(
        "mma.sync.aligned.m16n8k16.row.col.f32.f16.f16.f32 "
        "{%0,%1,%2,%3}, {%4,%5,%6,%7}, {%8,%9}, {%0,%1,%2,%3};"
        : "+f"(c[0]), "+f"(c[1]), "+f"(c[2]), "+f"(c[3])
        : "r"(a[0]), "r"(a[1]), "r"(a[2]), "r"(a[3]), "r"(b[0]), "r"(b[1]));
}

__device__ void gemm_body(char* smem, const float* __restrict__ ce) {
    uint32_t sb;
    asm("{ .reg .u64 t; cvta.to.shared.u64 t, %1; cvt.u32.u64 %0, t; }"
        : "=r"(sb) : "l"(smem));
    const int t = threadIdx.x;
    const int lane = t & 31, w = t >> 5;
    const int wm = w & 1, wn = w >> 1;     // 2 x 4 warps; warp tile 32 x 64
    const int m0 = blockIdx.x * 64;

    // A ldsm addressing (rows of 128B = 64 halves)
    const int arow0 = wm * 32 + (lane & 7) + ((lane >> 3) & 1) * 8;
    const uint32_t axor = (uint32_t)((arow0 & 7) << 4);
    const uint32_t khA = (uint32_t)((lane >> 4) * 16);
    // B ldsm addressing (rows of 128B = 64 halves)
    const int brow0 = wn * 64 + (lane & 7) + ((lane >> 4) & 1) * 8;
    const uint32_t bxor = (uint32_t)((lane & 7) << 4);
    const uint32_t khB = (uint32_t)(((lane >> 3) & 1) * 16);
    uint32_t arowb[2], browb[4];
#pragma unroll
    for (int i = 0; i < 2; i++) arowb[i] = (uint32_t)(arow0 + i * 16) * 128;
#pragma unroll
    for (int jp = 0; jp < 4; jp++) browb[jp] = (uint32_t)(brow0 + jp * 16) * 128;

    // A LDG/STS mapping: row = t>>2 (0..63), colgroup = t&3 (16 floats each)
    const int prow = t >> 2, pcg = t & 3;
    const uint32_t prx = (uint32_t)((prow & 7) << 4);
    // B cp.async mapping: 256 rows x 8 chunks of 16B
    const int bro = t >> 3, bo = t & 7;

    float acc[2][8][4];
#pragma unroll
    for (int i = 0; i < 2; i++)
#pragma unroll
        for (int j = 0; j < 8; j++)
#pragma unroll
            for (int q = 0; q < 4; q++) acc[i][j][q] = 0.f;

    float4 av[4];

    auto loadB = [&](int s, int buf) {
        const size_t kg = (size_t)s * 64;
        const uint32_t db = sb + buf * SST + BOFF;
#pragma unroll
        for (int i = 0; i < 8; i++) {
            int row = bro + i * 32;
            uint32_t so = (uint32_t)row * 128 +
                          (((uint32_t)bo * 16) ^ ((uint32_t)(row & 7) << 4));
            cpa16(db + so, g_WThi + (size_t)row * KTOT + kg + bo * 8);
        }
    };
    auto loadA = [&](int s) {
        const int a = s >> 2, kin = (s & 3) * 64;
        const float* p = ce + ((size_t)a * BATCH + m0 + prow) * D_MODEL + kin + pcg * 16;
#pragma unroll
        for (int q = 0; q < 4; q++) av[q] = *(const float4*)(p + q * 4);
    };
    auto stsA = [&](int buf) {
        const uint32_t da = sb + buf * SST;
        const uint32_t rbase = (uint32_t)prow * 128;
        uint32_t hv[8];
#pragma unroll
        for (int q = 0; q < 4; q++) {
            __half2 h01 = __floats2half2_rn(av[q].x, av[q].y);
            __half2 h23 = __floats2half2_rn(av[q].z, av[q].w);
            hv[2 * q]     = *(uint32_t*)&h01;
            hv[2 * q + 1] = *(uint32_t*)&h23;
        }
#pragma unroll
        for (int q = 0; q < 2; q++) {
            uint32_t off = rbase + (((uint32_t)(pcg * 32 + q * 16)) ^ prx);
            asm volatile("st.shared.v4.b32 [%0], {%1,%2,%3,%4};"
                         :: "r"(da + off), "r"(hv[4 * q]), "r"(hv[4 * q + 1]),
                            "r"(hv[4 * q + 2]), "r"(hv[4 * q + 3]));
        }
    };
    auto compute = [&](int buf) {
        const uint32_t SA = sb + buf * SST;
        const uint32_t SB = sb + buf * SST + BOFF;
#pragma unroll
        for (int kk = 0; kk < 4; kk++) {
            uint32_t ah[2][4], bh[4][4];
            const uint32_t ka = ((uint32_t)(kk * 32) + khA) ^ axor;
            const uint32_t kb = ((uint32_t)(kk * 32) + khB) ^ bxor;
#pragma unroll
            for (int i = 0; i < 2; i++) ldsm4(ah[i], SA + arowb[i] + ka);
#pragma unroll
            for (int jp = 0; jp < 4; jp++) ldsm4(bh[jp], SB + browb[jp] + kb);
#pragma unroll
            for (int i = 0; i < 2; i++)
#pragma unroll
                for (int j = 0; j < 8; j++)
                    mma_fp16(acc[i][j], ah[i], &bh[j >> 1][(j & 1) * 2]);
        }
    };

    // prologue
    loadB(0, 0);
    loadA(0);
    stsA(0);
    asm volatile("cp.async.commit_group;" ::: "memory");
    asm volatile("cp.async.wait_group 0;" ::: "memory");
    __syncthreads();

    for (int s = 0; s < 128; s++) {
        const int buf = s & 1, nxt = buf ^ 1;
        if (s + 1 < 128) { loadB(s + 1, nxt); loadA(s + 1); }
        compute(buf);
        if (s + 1 < 128) {
            stsA(nxt);
            asm volatile("cp.async.commit_group;" ::: "memory");
            asm volatile("cp.async.wait_group 0;" ::: "memory");
        }
        __syncthreads();
    }

    // write h
#pragma unroll
    for (int i = 0; i < 2; i++)
#pragma unroll
        for (int j = 0; j < 8; j++) {
            const int r = m0 + wm * 32 + i * 16 + (lane >> 2);
            const int c = wn * 64 + j * 8 + (lane & 3) * 2;
            *(float2*)(g_h + (size_t)r * D_MODEL + c) =
                make_float2(acc[i][j][0], acc[i][j][1]);
            *(float2*)(g_h + (size_t)(r + 8) * D_MODEL + c) =
                make_float2(acc[i][j][2], acc[i][j][3]);
        }
}

__device__ void dp_body(int a, char* sbuf,
                        const float* __restrict__ depth_emb,
                        const float* __restrict__ idx_emb,
                        const float* __restrict__ W) {
    float* de_s = (float*)sbuf;              // 15*256
    float* ie_s = de_s + NDEPTH * D_MODEL;   // 256
    const int j = threadIdx.x;
    for (int i = j; i < NDEPTH * D_MODEL; i += blockDim.x) de_s[i] = depth_emb[i];
    ie_s[j] = idx_emb[a * D_MODEL + j];
    __syncthreads();

    float acc[NDEPTH];
#pragma unroll
    for (int m = 0; m < NDEPTH; m++) acc[m] = 0.f;
    float acci = 0.f;
    const float* Wde = W + (size_t)(512 + a * 768) * D_MODEL + j;
    const float* Wie = W + (size_t)(768 + a * 768) * D_MODEL + j;
#pragma unroll 8
    for (int k = 0; k < D_MODEL; k++) {
        float wde = Wde[k * D_MODEL];
        float wie = Wie[k * D_MODEL];
        acci = fmaf(ie_s[k], wie, acci);
#pragma unroll
        for (int m = 0; m < NDEPTH; m++)
            acc[m] = fmaf(de_s[m * D_MODEL + k], wde, acc[m]);
    }
#pragma unroll
    for (int m = 0; m < NDEPTH; m++)
        g_DP[(a * NDEPTH + m) * D_MODEL + j] = acc[m] + acci;
}

__device__ void tp_body(int blk, char* sbuf,
                        const float* __restrict__ token_emb,
                        const float* __restrict__ W,
                        const float* __restrict__ bvec) {
    float* te_s = (float*)sbuf;  // 8*256
    const int v0 = blk * 8;
    const int j = threadIdx.x;
#pragma unroll
    for (int m = 0; m < 8; m++) {
        int v = v0 + m;
        te_s[m * D_MODEL + j] = (v < VOCAB) ? token_emb[v * D_MODEL + j] : 0.f;
    }
    __syncthreads();
    float acc[8];
    float bj = bvec[j];
#pragma unroll
    for (int m = 0; m < 8; m++) acc[m] = bj;
    const float* Wt = W + j;
#pragma unroll 8
    for (int k = 0; k < D_MODEL; k++) {
        float w = Wt[k * D_MODEL];
#pragma unroll
        for (int m = 0; m < 8; m++)
            acc[m] = fmaf(te_s[m * D_MODEL + k], w, acc[m]);
    }
#pragma unroll
    for (int m = 0; m < 8; m++) {
        int v = v0 + m;
        if (v < VOCAB) g_TP[v * D_MODEL + j] = acc[m];
    }
}

__global__ __launch_bounds__(256, 1)
void mega_kernel(const float* __restrict__ ce,
                 const float* __restrict__ depth_emb,
                 const float* __restrict__ idx_emb,
                 const float* __restrict__ token_emb,
                 const float* __restrict__ W,
                 const float* __restrict__ bvec) {
    extern __shared__ char smem[];
    const int b = blockIdx.x;
    if (b < GEMM_BLOCKS) gemm_body(smem, ce);
    else if (b < GEMM_BLOCKS + DP_BLOCKS) dp_body(b - GEMM_BLOCKS, smem, depth_emb, idx_emb, W);
    else tp_body(b - GEMM_BLOCKS - DP_BLOCKS, smem, token_emb, W, bvec);
}

// ---------------- fused bias-gather + ReLU + LayerNorm ------------------------
__global__ __launch_bounds__(256)
void ln_kernel(const int* __restrict__ nid, const int* __restrict__ cdep,
               const float* __restrict__ ln_g, const float* __restrict__ ln_b,
               float* __restrict__ out) {
    const int r = blockIdx.x * 8 + (threadIdx.x >> 5);
    const int lane = threadIdx.x & 31;
    const int cb = lane * 8;

    float4 x0 = *(const float4*)(g_h + (size_t)r * D_MODEL + cb);
    float4 x1 = *(const float4*)(g_h + (size_t)r * D_MODEL + cb + 4);
    const int tkn = nid[r];
    {
        const float* p = g_TP + tkn * D_MODEL + cb;
        float4 b0 = *(const float4*)p, b1 = *(const float4*)(p + 4);
        x0.x += b0.x; x0.y += b0.y; x0.z += b0.z; x0.w += b0.w;
        x1.x += b1.x; x1.y += b1.y; x1.z += b1.z; x1.w += b1.w;
    }
#pragma unroll
    for (int a = 0; a < ARITY; a++) {
        const int d = cdep[a * BATCH + r];
        const float* p = g_DP + (a * NDEPTH + d) * D_MODEL + cb;
        float4 b0 = *(const float4*)p, b1 = *(const float4*)(p + 4);
        x0.x += b0.x; x0.y += b0.y; x0.z += b0.z; x0.w += b0.w;
        x1.x += b1.x; x1.y += b1.y; x1.z += b1.z; x1.w += b1.w;
    }
    float h[8] = {x0.x, x0.y, x0.z, x0.w, x1.x, x1.y, x1.z, x1.w};
    float s = 0.f, ss = 0.f;
#pragma unroll
    for (int j = 0; j < 8; j++) {
        h[j] = fmaxf(h[j], 0.f);
        s += h[j];
        ss = fmaf(h[j], h[j], ss);
    }
#pragma unroll
    for (int o = 16; o > 0; o >>= 1) {
        s += __shfl_xor_sync(0xFFFFFFFFu, s, o);
        ss += __shfl_xor_sync(0xFFFFFFFFu, ss, o);
    }
    const float mu = s * (1.f / 256.f);
    const float rs = rsqrtf(ss * (1.f / 256.f) - mu * mu + LN_EPS);

    float4 g0 = *(const float4*)(ln_g + cb), g1 = *(const float4*)(ln_g + cb + 4);
    float4 l0 = *(const float4*)(ln_b + cb), l1 = *(const float4*)(ln_b + cb + 4);
    float4 o0, o1;
    o0.x = (h[0] - mu) * rs * g0.x + l0.x;
    o0.y = (h[1] - mu) * rs * g0.y + l0.y;
    o0.z = (h[2] - mu) * rs * g0.z + l0.z;
    o0.w = (h[3] - mu) * rs * g0.w + l0.w;
    o1.x = (h[4] - mu) * rs * g1.x + l1.x;
    o1.y = (h[5] - mu) * rs * g1.y + l1.y;
    o1.z = (h[6] - mu) * rs * g1.z + l1.z;
    o1.w = (h[7] - mu) * rs * g1.w + l1.w;
    *(float4*)(out + (size_t)r * D_MODEL + cb) = o0;
    *(float4*)(out + (size_t)r * D_MODEL + cb + 4) = o1;
}

// --------------------------------- launch -------------------------------------
extern "C" void kernel_launch(void* const* d_in, const int* in_sizes, int n_in,
                              void* d_out, int out_size) {
    const int*   nid          = (const int*)d_in[0];
    const float* child_embs   = (const float*)d_in[1];
    const int*   child_depths = (const int*)d_in[2];
    const float* token_emb    = (const float*)d_in[3];
    const float* depth_emb    = (const float*)d_in[4];
    const float* idx_emb      = (const float*)d_in[5];
    const float* W            = (const float*)d_in[6];
    const float* bvec         = (const float*)d_in[7];
    const float* ln_g         = (const float*)d_in[8];
    const float* ln_b         = (const float*)d_in[9];
    float* out = (float*)d_out;

    cudaFuncSetAttribute(mega_kernel, cudaFuncAttributeMaxDynamicSharedMemorySize, SMEM_BYTES);

    convW_kernel<<<KTOT / 32, 256>>>(W);
    mega_kernel<<<GEMM_BLOCKS + DP_BLOCKS + TP_BLOCKS, 256, SMEM_BYTES>>>(
        child_embs, depth_emb, idx_emb, token_emb, W, bvec);
    ln_kernel<<<BATCH / 8, 256>>>(nid, child_depths, ln_g, ln_b, out);
}

// round 7
// speedup vs baseline: 7.2738x; 1.1193x over previous
#include <cuda_runtime.h>
#include <cuda_fp16.h>
#include <cstdint>

#define D_MODEL 256
#define ARITY 32
#define NDEPTH 15
#define VOCAB 1027
#define BATCH 8192
#define KTOT 8192
#define LN_EPS 1e-5f

// ------------------------- device scratch (no allocs allowed) -----------------
__device__ __align__(16) __half g_TPh[VOCAB * D_MODEL];           // token proj + b (fp16)
__device__ __align__(16) __half g_DPh[ARITY * NDEPTH * D_MODEL];  // depth+idx proj (fp16)
__device__ __align__(16) __half g_WThi[(size_t)D_MODEL * KTOT];   // W child blocks, transposed
__device__ int g_done;

// W layout (row-major [24832, 256]):
//   rows [0,256)                     : token block
//   rows 256 + a*768 + [0,256)       : child-emb block a   (the real GEMM)
//   rows 256 + a*768 + 256 + [0,256) : depth block a
//   rows 256 + a*768 + 512 + [0,256) : idx block a

// ---------------- convW: convert+transpose W child blocks -> WThi [256 x 8192] -
// also resets g_done (runs before mega in stream order, every graph replay)
__global__ __launch_bounds__(256)
void convW_kernel(const float* __restrict__ W) {
    if (blockIdx.x == 0 && threadIdx.x == 0) g_done = 0;
    __shared__ float ws[32][257];
    const int kc = blockIdx.x * 32;
    const int t = threadIdx.x;
#pragma unroll 8
    for (int r = 0; r < 32; r++) {
        int kg = kc + r;
        ws[r][t] = W[(size_t)(256 + (kg >> 8) * 768 + (kg & 255)) * D_MODEL + t];
    }
    __syncthreads();
    uint32_t hi[16];
#pragma unroll
    for (int p = 0; p < 16; p++) {
        __half2 h = __floats2half2_rn(ws[2 * p][t], ws[2 * p + 1][t]);
        hi[p] = *(uint32_t*)&h;
    }
    uint4* ph = (uint4*)(g_WThi + (size_t)t * KTOT + kc);
#pragma unroll
    for (int q = 0; q < 4; q++)
        ph[q] = make_uint4(hi[4 * q], hi[4 * q + 1], hi[4 * q + 2], hi[4 * q + 3]);
}

// ================================ mega kernel ==================================
// blocks [0,128): GEMM + fused bias/ReLU/LN epilogue
// blocks [128,160): dp bodies   blocks [160,289): tp bodies
#define GEMM_BLOCKS 128
#define DP_BLOCKS 32
#define TP_BLOCKS 129
#define PREP_TOTAL (DP_BLOCKS + TP_BLOCKS)
#define SST 40960
#define BOFF 8192
#define SMEM_BYTES 81920

__device__ __forceinline__ void cpa16(uint32_t s, const void* g) {
    asm volatile("cp.async.cg.shared.global [%0], [%1], 16;" :: "r"(s), "l"(g));
}
__device__ __forceinline__ void ldsm4(uint32_t* r, uint32_t a) {
    asm volatile("ldmatrix.sync.aligned.m8n8.x4.shared.b16 {%0,%1,%2,%3}, [%4];"
                 : "=r"(r[0]), "=r"(r[1]), "=r"(r[2]), "=r"(r[3]) : "r"(a));
}
__device__ __forceinline__ void mma_fp16(float* c, const uint32_t* a, const uint32_t* b) {
    asm volatile(
        "mma.sync.aligned.m16n8k16.row.col.f32.f16.f16.f32 "
        "{%0,%1,%2,%3}, {%4,%5,%6,%7}, {%8,%9}, {%0,%1,%2,%3};"
        : "+f"(c[0]), "+f"(c[1]), "+f"(c[2]), "+f"(c[3])
        : "r"(a[0]), "r"(a[1]), "r"(a[2]), "r"(a[3]), "r"(b[0]), "r"(b[1]));
}
__device__ __forceinline__ int ld_acq(const int* p) {
    int v;
    asm volatile("ld.acquire.gpu.s32 %0, [%1];" : "=r"(v) : "l"(p));
    return v;
}
__device__ __forceinline__ void add_half8(float* hb, uint4 v) {
    const __half2* q = (const __half2*)&v;
#pragma unroll
    for (int p = 0; p < 4; p++) {
        float2 f = __half22float2(q[p]);
        hb[2 * p] += f.x;
        hb[2 * p + 1] += f.y;
    }
}

__device__ void gemm_body(char* smem, const float* __restrict__ ce,
                          const int* __restrict__ nid, const int* __restrict__ cdep,
                          const float* __restrict__ ln_g, const float* __restrict__ ln_b,
                          float* __restrict__ out) {
    uint32_t sb;
    asm("{ .reg .u64 t; cvta.to.shared.u64 t, %1; cvt.u32.u64 %0, t; }"
        : "=r"(sb) : "l"(smem));
    const int t = threadIdx.x;
    const int lane = t & 31, w = t >> 5;
    const int wm = w & 1, wn = w >> 1;     // 2 x 4 warps; warp tile 32 x 64
    const int m0 = blockIdx.x * 64;

    // A ldsm addressing
    const int arow0 = wm * 32 + (lane & 7) + ((lane >> 3) & 1) * 8;
    const uint32_t axor = (uint32_t)((arow0 & 7) << 4);
    const uint32_t khA = (uint32_t)((lane >> 4) * 16);
    // B ldsm addressing
    const int brow0 = wn * 64 + (lane & 7) + ((lane >> 4) & 1) * 8;
    const uint32_t bxor = (uint32_t)((lane & 7) << 4);
    const uint32_t khB = (uint32_t)(((lane >> 3) & 1) * 16);
    uint32_t arowb[2], browb[4];
#pragma unroll
    for (int i = 0; i < 2; i++) arowb[i] = (uint32_t)(arow0 + i * 16) * 128;
#pragma unroll
    for (int jp = 0; jp < 4; jp++) browb[jp] = (uint32_t)(brow0 + jp * 16) * 128;

    // A LDG/STS mapping
    const int prow = t >> 2, pcg = t & 3;
    const uint32_t prx = (uint32_t)((prow & 7) << 4);
    // B cp.async mapping
    const int bro = t >> 3, bo = t & 7;

    float acc[2][8][4];
#pragma unroll
    for (int i = 0; i < 2; i++)
#pragma unroll
        for (int j = 0; j < 8; j++)
#pragma unroll
            for (int q = 0; q < 4; q++) acc[i][j][q] = 0.f;

    float4 av[4];

    auto loadB = [&](int s, int buf) {
        const size_t kg = (size_t)s * 64;
        const uint32_t db = sb + buf * SST + BOFF;
#pragma unroll
        for (int i = 0; i < 8; i++) {
            int row = bro + i * 32;
            uint32_t so = (uint32_t)row * 128 +
                          (((uint32_t)bo * 16) ^ ((uint32_t)(row & 7) << 4));
            cpa16(db + so, g_WThi + (size_t)row * KTOT + kg + bo * 8);
        }
    };
    auto loadA = [&](int s) {
        const int a = s >> 2, kin = (s & 3) * 64;
        const float* p = ce + ((size_t)a * BATCH + m0 + prow) * D_MODEL + kin + pcg * 16;
#pragma unroll
        for (int q = 0; q < 4; q++) av[q] = *(const float4*)(p + q * 4);
    };
    auto stsA = [&](int buf) {
        const uint32_t da = sb + buf * SST;
        const uint32_t rbase = (uint32_t)prow * 128;
        uint32_t hv[8];
#pragma unroll
        for (int q = 0; q < 4; q++) {
            __half2 h01 = __floats2half2_rn(av[q].x, av[q].y);
            __half2 h23 = __floats2half2_rn(av[q].z, av[q].w);
            hv[2 * q]     = *(uint32_t*)&h01;
            hv[2 * q + 1] = *(uint32_t*)&h23;
        }
#pragma unroll
        for (int q = 0; q < 2; q++) {
            uint32_t off = rbase + (((uint32_t)(pcg * 32 + q * 16)) ^ prx);
            asm volatile("st.shared.v4.b32 [%0], {%1,%2,%3,%4};"
                         :: "r"(da + off), "r"(hv[4 * q]), "r"(hv[4 * q + 1]),
                            "r"(hv[4 * q + 2]), "r"(hv[4 * q + 3]));
        }
    };
    auto compute = [&](int buf) {
        const uint32_t SA = sb + buf * SST;
        const uint32_t SB = sb + buf * SST + BOFF;
#pragma unroll
        for (int kk = 0; kk < 4; kk++) {
            uint32_t ah[2][4], bh[4][4];
            const uint32_t ka = ((uint32_t)(kk * 32) + khA) ^ axor;
            const uint32_t kb = ((uint32_t)(kk * 32) + khB) ^ bxor;
#pragma unroll
            for (int i = 0; i < 2; i++) ldsm4(ah[i], SA + arowb[i] + ka);
#pragma unroll
            for (int jp = 0; jp < 4; jp++) ldsm4(bh[jp], SB + browb[jp] + kb);
#pragma unroll
            for (int i = 0; i < 2; i++)
#pragma unroll
                for (int j = 0; j < 8; j++)
                    mma_fp16(acc[i][j], ah[i], &bh[j >> 1][(j & 1) * 2]);
        }
    };

    // prologue
    loadB(0, 0);
    loadA(0);
    stsA(0);
    asm volatile("cp.async.commit_group;" ::: "memory");
    asm volatile("cp.async.wait_group 0;" ::: "memory");
    __syncthreads();

    for (int s = 0; s < 128; s++) {
        const int buf = s & 1, nxt = buf ^ 1;
        if (s + 1 < 128) { loadB(s + 1, nxt); loadA(s + 1); }
        compute(buf);
        if (s + 1 < 128) {
            stsA(nxt);
            asm volatile("cp.async.commit_group;" ::: "memory");
            asm volatile("cp.async.wait_group 0;" ::: "memory");
        }
        __syncthreads();
    }

    // ---------------- fused epilogue: stage -> smem, gather bias, ReLU, LN ----
    float* sh = (float*)smem;  // [64][260]
    {
        const int rb = wm * 32 + (lane >> 2);
        const int cb = wn * 64 + (lane & 3) * 2;
#pragma unroll
        for (int i = 0; i < 2; i++)
#pragma unroll
            for (int j = 0; j < 8; j++) {
                const int rr = rb + i * 16;
                const int cc = cb + j * 8;
                sh[rr * 260 + cc]           = acc[i][j][0];
                sh[rr * 260 + cc + 1]       = acc[i][j][1];
                sh[(rr + 8) * 260 + cc]     = acc[i][j][2];
                sh[(rr + 8) * 260 + cc + 1] = acc[i][j][3];
            }
    }
    // wait until dp/tp table blocks are done
    if (t == 0) {
        while (ld_acq(&g_done) < PREP_TOTAL) __nanosleep(64);
    }
    __syncthreads();

    // warp w handles rows [w*8, w*8+8)
    const int cb = lane * 8;
    float4 gg0 = *(const float4*)(ln_g + cb), gg1 = *(const float4*)(ln_g + cb + 4);
    float4 bb0 = *(const float4*)(ln_b + cb), bb1 = *(const float4*)(ln_b + cb + 4);
    const float gj[8] = {gg0.x, gg0.y, gg0.z, gg0.w, gg1.x, gg1.y, gg1.z, gg1.w};
    const float lj[8] = {bb0.x, bb0.y, bb0.z, bb0.w, bb1.x, bb1.y, bb1.z, bb1.w};

    int dvals[8];
#pragma unroll
    for (int q = 0; q < 8; q++)
        dvals[q] = cdep[(size_t)lane * BATCH + (m0 + w * 8 + q)];

#pragma unroll 2
    for (int q = 0; q < 8; q++) {
        const int r = m0 + w * 8 + q;
        float hb[8];
        const float* sp = sh + (w * 8 + q) * 260 + cb;
#pragma unroll
        for (int x = 0; x < 8; x++) hb[x] = sp[x];

        const int tk = nid[r];
        add_half8(hb, *(const uint4*)(g_TPh + tk * D_MODEL + cb));
#pragma unroll
        for (int a = 0; a < ARITY; a++) {
            const int d = __shfl_sync(0xFFFFFFFFu, dvals[q], a);
            add_half8(hb, *(const uint4*)(g_DPh + ((a * NDEPTH + d) << 8) + cb));
        }

        float s = 0.f, ss = 0.f;
#pragma unroll
        for (int x = 0; x < 8; x++) {
            hb[x] = fmaxf(hb[x], 0.f);
            s += hb[x];
            ss = fmaf(hb[x], hb[x], ss);
        }
#pragma unroll
        for (int o = 16; o > 0; o >>= 1) {
            s  += __shfl_xor_sync(0xFFFFFFFFu, s, o);
            ss += __shfl_xor_sync(0xFFFFFFFFu, ss, o);
        }
        const float mu = s * (1.f / 256.f);
        const float rs = rsqrtf(ss * (1.f / 256.f) - mu * mu + LN_EPS);

        float4 o0, o1;
        o0.x = (hb[0] - mu) * rs * gj[0] + lj[0];
        o0.y = (hb[1] - mu) * rs * gj[1] + lj[1];
        o0.z = (hb[2] - mu) * rs * gj[2] + lj[2];
        o0.w = (hb[3] - mu) * rs * gj[3] + lj[3];
        o1.x = (hb[4] - mu) * rs * gj[4] + lj[4];
        o1.y = (hb[5] - mu) * rs * gj[5] + lj[5];
        o1.z = (hb[6] - mu) * rs * gj[6] + lj[6];
        o1.w = (hb[7] - mu) * rs * gj[7] + lj[7];
        *(float4*)(out + (size_t)r * D_MODEL + cb)     = o0;
        *(float4*)(out + (size_t)r * D_MODEL + cb + 4) = o1;
    }
}

__device__ void dp_body(int a, char* sbuf,
                        const float* __restrict__ depth_emb,
                        const float* __restrict__ idx_emb,
                        const float* __restrict__ W) {
    float* de_s = (float*)sbuf;              // 15*256
    float* ie_s = de_s + NDEPTH * D_MODEL;   // 256
    const int j = threadIdx.x;
    for (int i = j; i < NDEPTH * D_MODEL; i += blockDim.x) de_s[i] = depth_emb[i];
    ie_s[j] = idx_emb[a * D_MODEL + j];
    __syncthreads();

    float acc[NDEPTH];
#pragma unroll
    for (int m = 0; m < NDEPTH; m++) acc[m] = 0.f;
    float acci = 0.f;
    const float* Wde = W + (size_t)(512 + a * 768) * D_MODEL + j;
    const float* Wie = W + (size_t)(768 + a * 768) * D_MODEL + j;
#pragma unroll 8
    for (int k = 0; k < D_MODEL; k++) {
        float wde = Wde[k * D_MODEL];
        float wie = Wie[k * D_MODEL];
        acci = fmaf(ie_s[k], wie, acci);
#pragma unroll
        for (int m = 0; m < NDEPTH; m++)
            acc[m] = fmaf(de_s[m * D_MODEL + k], wde, acc[m]);
    }
#pragma unroll
    for (int m = 0; m < NDEPTH; m++)
        g_DPh[(a * NDEPTH + m) * D_MODEL + j] = __float2half_rn(acc[m] + acci);

    __syncthreads();
    __threadfence();
    if (threadIdx.x == 0) atomicAdd(&g_done, 1);
}

__device__ void tp_body(int blk, char* sbuf,
                        const float* __restrict__ token_emb,
                        const float* __restrict__ W,
                        const float* __restrict__ bvec) {
    float* te_s = (float*)sbuf;  // 8*256
    const int v0 = blk * 8;
    const int j = threadIdx.x;
#pragma unroll
    for (int m = 0; m < 8; m++) {
        int v = v0 + m;
        te_s[m * D_MODEL + j] = (v < VOCAB) ? token_emb[v * D_MODEL + j] : 0.f;
    }
    __syncthreads();
    float acc[8];
    float bj = bvec[j];
#pragma unroll
    for (int m = 0; m < 8; m++) acc[m] = bj;
    const float* Wt = W + j;
#pragma unroll 8
    for (int k = 0; k < D_MODEL; k++) {
        float w = Wt[k * D_MODEL];
#pragma unroll
        for (int m = 0; m < 8; m++)
            acc[m] = fmaf(te_s[m * D_MODEL + k], w, acc[m]);
    }
#pragma unroll
    for (int m = 0; m < 8; m++) {
        int v = v0 + m;
        if (v < VOCAB) g_TPh[v * D_MODEL + j] = __float2half_rn(acc[m]);
    }
    __syncthreads();
    __threadfence();
    if (threadIdx.x == 0) atomicAdd(&g_done, 1);
}

__global__ __launch_bounds__(256, 1)
void mega_kernel(const float* __restrict__ ce,
                 const float* __restrict__ depth_emb,
                 const float* __restrict__ idx_emb,
                 const float* __restrict__ token_emb,
                 const float* __restrict__ W,
                 const float* __restrict__ bvec,
                 const int* __restrict__ nid,
                 const int* __restrict__ cdep,
                 const float* __restrict__ ln_g,
                 const float* __restrict__ ln_b,
                 float* __restrict__ out) {
    extern __shared__ char smem[];
    const int b = blockIdx.x;
    if (b < GEMM_BLOCKS) gemm_body(smem, ce, nid, cdep, ln_g, ln_b, out);
    else if (b < GEMM_BLOCKS + DP_BLOCKS) dp_body(b - GEMM_BLOCKS, smem, depth_emb, idx_emb, W);
    else tp_body(b - GEMM_BLOCKS - DP_BLOCKS, smem, token_emb, W, bvec);
}

// --------------------------------- launch -------------------------------------
extern "C" void kernel_launch(void* const* d_in, const int* in_sizes, int n_in,
                              void* d_out, int out_size) {
    const int*   nid          = (const int*)d_in[0];
    const float* child_embs   = (const float*)d_in[1];
    const int*   child_depths = (const int*)d_in[2];
    const float* token_emb    = (const float*)d_in[3];
    const float* depth_emb    = (const float*)d_in[4];
    const float* idx_emb      = (const float*)d_in[5];
    const float* W            = (const float*)d_in[6];
    const float* bvec         = (const float*)d_in[7];
    const float* ln_g         = (const float*)d_in[8];
    const float* ln_b         = (const float*)d_in[9];
    float* out = (float*)d_out;

    cudaFuncSetAttribute(mega_kernel, cudaFuncAttributeMaxDynamicSharedMemorySize, SMEM_BYTES);

    convW_kernel<<<KTOT / 32, 256>>>(W);
    mega_kernel<<<GEMM_BLOCKS + DP_BLOCKS + TP_BLOCKS, 256, SMEM_BYTES>>>(
        child_embs, depth_emb, idx_emb, token_emb, W, bvec,
        nid, child_depths, ln_g, ln_b, out);
}